// round 7
// baseline (speedup 1.0000x reference)
#include <cuda_runtime.h>
#include <math_constants.h>
#include <cstdint>

#define NLEV 1024
#define KP1  9
#define NB   8192
#define MAIN_THREADS 1024
#define NBLOCKS 304

// Global scratch (allocation-free)
__device__ float  g_mid[NLEV];      // midpoints; g_mid[1023] = +INF sentinel
__device__ float  g_lut[NLEV];      // per-nidx output value
__device__ float2 g_tabA[NB];       // {split (+INF if none), vlo}
__device__ float  g_tabB[NB];       // vhi, or sentinel < thresh encoding pos
__device__ float  g_scale, g_ofs, g_thresh;

// Monotone bucket map — MUST be bit-identical in setup and main.
__device__ __forceinline__ int bucket_of(float x, float scale, float ofs) {
    float v = __fmaf_rn(x, scale, ofs);
    v = fminf(fmaxf(v, 0.0f), (float)(NB - 1));
    return (int)v;
}

// ---------------------------------------------------------------------------
// Fused setup: one block, 1024 threads.
// Reference loop uses h[:,0] for t=1 and h[:,t] for t=2..8 (column 1 unused).
// ---------------------------------------------------------------------------
__global__ void __launch_bounds__(NLEV)
setup_all(const float* __restrict__ h,
          const float* __restrict__ d,
          const float* __restrict__ T,
          const float* __restrict__ b) {
    __shared__ float s_h[NLEV * KP1];   // 36 KB (reused as reduce buffer later)
    __shared__ float s_m[NLEV];
    __shared__ float s_lut[NLEV];
    __shared__ float s_params[3];       // scale, ofs, thresh

    int t = threadIdx.x;
    for (int j = t; j < NLEV * KP1; j += NLEV) s_h[j] = h[j];
    __syncthreads();

    float h0 = s_h[t * KP1];
    float acc = -b[0];
    acc += (h0 - T[1] >= 0.0f) ? d[1] : 0.0f;
#pragma unroll
    for (int k = 2; k <= 8; k++)
        acc += (s_h[t * KP1 + k] - T[k] >= 0.0f) ? d[k] : 0.0f;
    s_lut[t] = acc;
    g_lut[t] = acc;

    float m;
    if (t < NLEV - 1) m = 0.5f * (h0 + s_h[(t + 1) * KP1]);
    else              m = CUDART_INF_F;
    s_m[t] = m;
    g_mid[t] = m;
    __syncthreads();

    // min-reduce lut into s_h[0..1023] (reuse)
    s_h[t] = acc;
    __syncthreads();
#pragma unroll
    for (int s = 512; s >= 1; s >>= 1) {
        if (t < s) s_h[t] = fminf(s_h[t], s_h[t + s]);
        __syncthreads();
    }
    if (t == 0) {
        float lo = s_m[0], hi = s_m[NLEV - 2];
        float scale = (float)NB / (hi - lo);
        float ofs   = -lo * scale;
        float thr   = floorf(s_h[0]) - 4.0f;   // strictly below every lut value
        s_params[0] = scale; s_params[1] = ofs; s_params[2] = thr;
        g_scale = scale;     g_ofs = ofs;       g_thresh = thr;
    }
    __syncthreads();
    float scale = s_params[0], ofs = s_params[1], thr = s_params[2];

    // Build tables: 8 buckets per thread, coalesced stores.
#pragma unroll
    for (int j = 0; j < NB / NLEV; j++) {
        int bkt = t + j * NLEV;
        int pos = 0;
#pragma unroll
        for (int step = 512; step >= 1; step >>= 1) {
            float mv = s_m[pos + step - 1];
            if (bucket_of(mv, scale, ofs) < bkt) pos += step;
        }
        // pos = count of midpoints whose bucket < bkt (INF never counts)
        bool has   = (pos < NLEV - 1) && (bucket_of(s_m[pos], scale, ofs) == bkt);
        bool multi = has && (pos < NLEV - 2) && (bucket_of(s_m[pos + 1], scale, ofs) == bkt);
        float split = has ? s_m[pos] : CUDART_INF_F;
        float vlo   = s_lut[pos];
        float vhi;
        if (!has)       vhi = 0.0f;                       // never selected
        else if (multi) vhi = thr - 2.0f - (float)pos;    // sentinel < thr
        else            vhi = s_lut[pos + 1];
        g_tabA[bkt] = make_float2(split, vlo);
        g_tabB[bkt] = vhi;
    }
}

// ---------------------------------------------------------------------------
// Main kernel: branch-free 0/1-midpoint resolve; rare global scan for >=2.
// ---------------------------------------------------------------------------
__device__ __forceinline__ float eval_one(float xv, float scale, float ofs, float thr,
                                          const float2* __restrict__ s_tabA,
                                          const float*  __restrict__ s_tabB) {
    float v = __fmaf_rn(xv, scale, ofs);
    v = fminf(fmaxf(v, 0.0f), (float)(NB - 1));
    int bkt = (int)v;
    float2 e = s_tabA[bkt];
    float r = e.y;                          // vlo (94% of lanes final)
    if (xv >= e.x) {                        // ~6% of lanes
        float w = s_tabB[bkt];              // vhi or sentinel
        if (w < thr) {                      // ~0.4% of lanes: >=2 midpoints here
            int nidx = (int)(thr - 2.0f - w) + 1;
            while (g_mid[nidx] <= xv) nidx++;   // stops at +INF
            w = g_lut[nidx];
        }
        r = w;
    }
    return r;
}

__global__ void __launch_bounds__(MAIN_THREADS, 2)
ps_main(const float4* __restrict__ x, float4* __restrict__ out, int n4,
        const float* __restrict__ x_tail, float* __restrict__ out_tail, int ntail) {
    extern __shared__ char smem[];
    float2* s_tabA = (float2*)smem;                         // 64 KB
    float*  s_tabB = (float*)(smem + NB * sizeof(float2));  // 32 KB

    int tid = threadIdx.x;
    {   // coalesced table load as float4
        const float4* srcA = (const float4*)g_tabA;
        float4* dstA = (float4*)s_tabA;
        for (int j = tid; j < NB / 2; j += MAIN_THREADS) dstA[j] = srcA[j];
        const float4* srcB = (const float4*)g_tabB;
        float4* dstB = (float4*)s_tabB;
        for (int j = tid; j < NB / 4; j += MAIN_THREADS) dstB[j] = srcB[j];
    }
    float scale = g_scale, ofs = g_ofs, thr = g_thresh;
    __syncthreads();

    int stride = gridDim.x * MAIN_THREADS;
#pragma unroll 2
    for (int i = blockIdx.x * MAIN_THREADS + tid; i < n4; i += stride) {
        float4 v = x[i];
        float4 o;
        o.x = eval_one(v.x, scale, ofs, thr, s_tabA, s_tabB);
        o.y = eval_one(v.y, scale, ofs, thr, s_tabA, s_tabB);
        o.z = eval_one(v.z, scale, ofs, thr, s_tabA, s_tabB);
        o.w = eval_one(v.w, scale, ofs, thr, s_tabA, s_tabB);
        out[i] = o;
    }
    if (blockIdx.x == 0 && tid < ntail)
        out_tail[tid] = eval_one(x_tail[tid], scale, ofs, thr, s_tabA, s_tabB);
}

// ---------------------------------------------------------------------------
extern "C" void kernel_launch(void* const* d_in, const int* in_sizes, int n_in,
                              void* d_out, int out_size) {
    const float* x = (const float*)d_in[0];
    const float* h = (const float*)d_in[1];
    const float* d = (const float*)d_in[2];
    const float* T = (const float*)d_in[3];
    const float* b = (const float*)d_in[4];
    float* out = (float*)d_out;

    int n  = in_sizes[0];
    int n4 = n >> 2;
    int ntail = n - (n4 << 2);

    const int smem_bytes = NB * sizeof(float2) + NB * sizeof(float);  // 96 KB
    cudaFuncSetAttribute(ps_main, cudaFuncAttributeMaxDynamicSharedMemorySize, smem_bytes);

    setup_all<<<1, NLEV>>>(h, d, T, b);
    ps_main<<<NBLOCKS, MAIN_THREADS, smem_bytes>>>(
        (const float4*)x, (float4*)out, n4,
        x + (n4 << 2), out + (n4 << 2), ntail);
}